// round 13
// baseline (speedup 1.0000x reference)
#include <cuda_runtime.h>

#define NN 100000
#define NE 3200000
#define NF 128
#define NH 16
#define MH 100
#define NC 12
#define NG 512

#define SCAN_CHUNK 512
#define NBLK ((NN + SCAN_CHUNK - 1) / SCAN_CHUNK)   // 196
#define G_PLACE (NE / 256)                          // 12500 blocks, 1 edge/thread

// Scratch (allocation-free per harness rules)
__device__ __align__(16) float  g_dinv[NN];
__device__ __align__(16) int    g_degi[NN];
__device__ __align__(16) int    g_off[NN];
__device__ __align__(16) int    g_cursor[NN];
__device__ __align__(16) int    g_bsum[NBLK];
__device__ __align__(16) float  g_hA[NN * NH];
__device__ __align__(16) float  g_hB[NN * NH];
__device__ __align__(16) float  g_pool[NG * NH];
__device__ __align__(16) int    g_src32[NE];
__device__ __align__(16) int    g_dst32[NE];
__device__ __align__(16) float2 g_epack[NE];   // {src bits, norm}
__device__ int g_is64;

__device__ __forceinline__ void red_add_v4(float* addr, float4 v) {
    asm volatile("red.global.add.v4.f32 [%0], {%1,%2,%3,%4};"
                 :: "l"(addr), "f"(v.x), "f"(v.y), "f"(v.z), "f"(v.w)
                 : "memory");
}

// ---------------------------------------------------------------------------
// 1) setup: dtype probe (1 thread) + degi = 0 + pool = 0
__global__ void k_setup(const int* __restrict__ ei_raw) {
    int i = blockIdx.x * blockDim.x + threadIdx.x;
    if (i == 0) {
        int ok = 1;
        #pragma unroll
        for (int j = 1; j < 32; j += 2)
            if (ei_raw[j] != 0) ok = 0;
        g_is64 = ok;
    }
    if (i < NN) g_degi[i] = 0;
    if (i < NG * NH) g_pool[i] = 0.0f;
}

// 2) fused: index conversion + degree histogram (dst side). 2 edges/thread.
__global__ void k_cvt_deg(const void* __restrict__ ei) {
    int e = (blockIdx.x * blockDim.x + threadIdx.x) * 2;
    if (e >= NE) return;  // NE % 2 == 0
    int2 s32, d32;
    if (g_is64) {
        const long long* p = (const long long*)ei;
        longlong2 s = *(const longlong2*)(p + e);
        longlong2 d = *(const longlong2*)(p + NE + e);
        s32 = make_int2((int)s.x, (int)s.y);
        d32 = make_int2((int)d.x, (int)d.y);
    } else {
        const int* p = (const int*)ei;
        s32 = *(const int2*)(p + e);
        d32 = *(const int2*)(p + NE + e);
    }
    *(int2*)(g_src32 + e) = s32;
    *(int2*)(g_dst32 + e) = d32;
    atomicAdd(&g_degi[d32.x], 1);
    atomicAdd(&g_degi[d32.y], 1);
}

// ---------------------------------------------------------------------------
// 3) scan part 1 (per-block, 512 elems) + fused dinv = rsqrt(deg+1)
__global__ void k_scan1() {
    __shared__ int s[256];
    int t = threadIdx.x, b = blockIdx.x;
    int i0 = b * SCAN_CHUNK + t * 2;
    int a = (i0     < NN) ? g_degi[i0]     : 0;
    int c = (i0 + 1 < NN) ? g_degi[i0 + 1] : 0;
    if (i0     < NN) g_dinv[i0]     = rsqrtf((float)(a + 1));
    if (i0 + 1 < NN) g_dinv[i0 + 1] = rsqrtf((float)(c + 1));
    int pair = a + c;
    s[t] = pair;
    __syncthreads();
    for (int ofs = 1; ofs < 256; ofs <<= 1) {
        int v = (t >= ofs) ? s[t - ofs] : 0;
        __syncthreads();
        s[t] += v;
        __syncthreads();
    }
    int excl = s[t] - pair;
    if (i0     < NN) g_off[i0]     = excl;
    if (i0 + 1 < NN) g_off[i0 + 1] = excl + a;
    if (t == 255) g_bsum[b] = s[255];
}

// 4) scan parts 2+3 merged: every block re-scans the 196 block sums in smem
//    (duplicate compute, no extra kernel), then applies offsets to its 256
//    nodes and seeds the cursors.
__global__ void k_scan23() {
    __shared__ int sb[256];   // inclusive scan of bsum
    __shared__ int se[256];   // exclusive
    int t = threadIdx.x;
    int v = (t < NBLK) ? g_bsum[t] : 0;
    sb[t] = v;
    __syncthreads();
    for (int ofs = 1; ofs < 256; ofs <<= 1) {
        int u = (t >= ofs) ? sb[t - ofs] : 0;
        __syncthreads();
        sb[t] += u;
        __syncthreads();
    }
    se[t] = sb[t] - v;
    __syncthreads();

    int i = blockIdx.x * blockDim.x + t;
    if (i >= NN) return;
    int o = g_off[i] + se[i / SCAN_CHUNK];
    g_off[i] = o;
    g_cursor[i] = o;
}

// ---------------------------------------------------------------------------
// 5) fused independent work: blocks [0, G_PLACE) do edge placement,
//    blocks [G_PLACE, ...) compute g_hA = x @ W1.
__global__ void k_place_xw1(const float* __restrict__ x,
                            const float* __restrict__ W1) {
    __shared__ float sW[NF * NH];
    int bid = blockIdx.x;
    int t = threadIdx.x;

    if (bid < G_PLACE) {
        // ---- placement: bucket edges by dst, pack (src, norm)
        int e = bid * 256 + t;   // NE == G_PLACE*256 exactly
        int s = g_src32[e];
        int d = g_dst32[e];
        int pos = atomicAdd(&g_cursor[d], 1);
        float nm = g_dinv[s] * g_dinv[d];
        g_epack[pos] = make_float2(__int_as_float(s), nm);
        return;
    }

    // ---- xw1: 4 rows per thread, W1 in smem
    for (int i = t; i < NF * NH; i += blockDim.x) sW[i] = W1[i];
    __syncthreads();

    int r0 = ((bid - G_PLACE) * blockDim.x + t) * 4;
    if (r0 >= NN) return;   // NN % 4 == 0

    float acc[4][NH];
    #pragma unroll
    for (int r = 0; r < 4; r++)
        #pragma unroll
        for (int m = 0; m < NH; m++) acc[r][m] = 0.0f;

    const float4* x4 = (const float4*)x;
    const float4* sW4 = (const float4*)sW;

    for (int k4 = 0; k4 < NF / 4; k4++) {
        float4 xv[4];
        #pragma unroll
        for (int r = 0; r < 4; r++)
            xv[r] = x4[(size_t)(r0 + r) * (NF / 4) + k4];

        #pragma unroll
        for (int j = 0; j < 4; j++) {
            int k = k4 * 4 + j;
            #pragma unroll
            for (int m4 = 0; m4 < NH / 4; m4++) {
                float4 wv = sW4[k * (NH / 4) + m4];
                #pragma unroll
                for (int r = 0; r < 4; r++) {
                    float xs = (j == 0) ? xv[r].x : (j == 1) ? xv[r].y
                             : (j == 2) ? xv[r].z : xv[r].w;
                    acc[r][m4 * 4 + 0] += xs * wv.x;
                    acc[r][m4 * 4 + 1] += xs * wv.y;
                    acc[r][m4 * 4 + 2] += xs * wv.z;
                    acc[r][m4 * 4 + 3] += xs * wv.w;
                }
            }
        }
    }

    #pragma unroll
    for (int r = 0; r < 4; r++) {
        float4* o = (float4*)(g_hA + (size_t)(r0 + r) * NH);
        #pragma unroll
        for (int m4 = 0; m4 < NH / 4; m4++)
            o[m4] = make_float4(acc[r][m4 * 4 + 0], acc[r][m4 * 4 + 1],
                                acc[r][m4 * 4 + 2], acc[r][m4 * 4 + 3]);
    }
}

// ---------------------------------------------------------------------------
// 6) gather1: conv1 (bias + self loop + CSR gather over g_hA), then fused
//    relu + @W2 via warp shuffles. Writes g_hB = relu(conv1) @ W2.
__global__ void k_gather1(const float* __restrict__ bias,
                          const float* __restrict__ W2) {
    __shared__ float sW[NH * NH];
    if (threadIdx.x < NH * NH) sW[threadIdx.x] = W2[threadIdx.x];
    __syncthreads();

    int t = blockIdx.x * blockDim.x + threadIdx.x;
    if (t >= NN * 4) return;   // NN*4 = 400000 = 12500 full warps
    int n = t >> 2;
    int c = t & 3;
    int lane = threadIdx.x & 31;

    float di = g_dinv[n];
    float d2 = di * di;
    const float4* hin = (const float4*)g_hA;
    float4 h0 = hin[n * 4 + c];
    float4 bv = ((const float4*)bias)[c];
    float4 acc = make_float4(bv.x + d2 * h0.x, bv.y + d2 * h0.y,
                             bv.z + d2 * h0.z, bv.w + d2 * h0.w);

    int beg = g_off[n];
    int end = beg + g_degi[n];
    for (int e = beg; e < end; e++) {
        float2 p = __ldg(&g_epack[e]);
        int s = __float_as_int(p.x);
        float nm = p.y;
        float4 v = __ldg(&hin[s * 4 + c]);
        acc.x += nm * v.x;
        acc.y += nm * v.y;
        acc.z += nm * v.z;
        acc.w += nm * v.w;
    }

    float4 r = make_float4(fmaxf(acc.x, 0.f), fmaxf(acc.y, 0.f),
                           fmaxf(acc.z, 0.f), fmaxf(acc.w, 0.f));

    // collect full 16-feature row from the 4 sibling lanes
    float row[NH];
    int base = lane & ~3;
    #pragma unroll
    for (int cc = 0; cc < 4; cc++) {
        int sl = base + cc;
        row[cc * 4 + 0] = __shfl_sync(0xffffffffu, r.x, sl);
        row[cc * 4 + 1] = __shfl_sync(0xffffffffu, r.y, sl);
        row[cc * 4 + 2] = __shfl_sync(0xffffffffu, r.z, sl);
        row[cc * 4 + 3] = __shfl_sync(0xffffffffu, r.w, sl);
    }

    // out features [4c, 4c+4): o[m] = sum_k row[k] * W2[k][m]
    float4 o = make_float4(0.f, 0.f, 0.f, 0.f);
    #pragma unroll
    for (int k = 0; k < NH; k++) {
        float rk = row[k];
        const float* w = sW + k * NH + c * 4;
        o.x += rk * w[0];
        o.y += rk * w[1];
        o.z += rk * w[2];
        o.w += rk * w[3];
    }
    ((float4*)g_hB)[n * 4 + c] = o;
}

// ---------------------------------------------------------------------------
// 7) gather2: conv2 over g_hB + fused relu + global_add_pool.
__global__ void k_gather2(const float* __restrict__ bias,
                          const void* __restrict__ batch) {
    int t = blockIdx.x * blockDim.x + threadIdx.x;
    if (t >= NN * 4) return;   // warp-aligned boundary
    int n = t >> 2;
    int c = t & 3;
    int lane = threadIdx.x & 31;

    float di = g_dinv[n];
    float d2 = di * di;
    const float4* hin = (const float4*)g_hB;
    float4 h0 = hin[n * 4 + c];
    float4 bv = ((const float4*)bias)[c];
    float4 acc = make_float4(bv.x + d2 * h0.x, bv.y + d2 * h0.y,
                             bv.z + d2 * h0.z, bv.w + d2 * h0.w);

    int beg = g_off[n];
    int end = beg + g_degi[n];
    for (int e = beg; e < end; e++) {
        float2 p = __ldg(&g_epack[e]);
        int s = __float_as_int(p.x);
        float nm = p.y;
        float4 v = __ldg(&hin[s * 4 + c]);
        acc.x += nm * v.x;
        acc.y += nm * v.y;
        acc.z += nm * v.z;
        acc.w += nm * v.w;
    }

    float4 r = make_float4(fmaxf(acc.x, 0.f), fmaxf(acc.y, 0.f),
                           fmaxf(acc.z, 0.f), fmaxf(acc.w, 0.f));

    int b;
    if (g_is64) b = (int)((const long long*)batch)[n];
    else        b = ((const int*)batch)[n];

    // warp aggregation: if all 8 nodes in warp share one graph, reduce the
    // 8 same-chunk lanes and let lanes 0..3 emit a single RED each.
    int b0 = __shfl_sync(0xffffffffu, b, 0);
    bool uniform = __all_sync(0xffffffffu, b == b0);
    if (uniform) {
        #pragma unroll
        for (int m = 16; m >= 4; m >>= 1) {
            r.x += __shfl_xor_sync(0xffffffffu, r.x, m);
            r.y += __shfl_xor_sync(0xffffffffu, r.y, m);
            r.z += __shfl_xor_sync(0xffffffffu, r.z, m);
            r.w += __shfl_xor_sync(0xffffffffu, r.w, m);
        }
        if (lane < 4)
            red_add_v4(g_pool + (size_t)b0 * NH + lane * 4, r);
    } else {
        red_add_v4(g_pool + (size_t)b * NH + c * 4, r);
    }
}

// ---------------------------------------------------------------------------
// 8) MLP head: out = relu(relu(pool) @ lw1 + lb1) @ lw2 + lb2
__global__ void k_mlp(const float* __restrict__ lw1, const float* __restrict__ lb1,
                      const float* __restrict__ lw2, const float* __restrict__ lb2,
                      float* __restrict__ out) {
    __shared__ float sg[NH];
    __shared__ float sh[MH];
    int g = blockIdx.x;
    int t = threadIdx.x;
    if (t < NH) sg[t] = fmaxf(g_pool[(size_t)g * NH + t], 0.0f);
    __syncthreads();
    if (t < MH) {
        float a = lb1[t];
        #pragma unroll
        for (int i = 0; i < NH; i++) a += sg[i] * lw1[i * MH + t];
        sh[t] = fmaxf(a, 0.0f);
    }
    __syncthreads();
    if (t < NC) {
        float a = lb2[t];
        #pragma unroll 4
        for (int i = 0; i < MH; i++) a += sh[i] * lw2[i * NC + t];
        out[(size_t)g * NC + t] = a;
    }
}

// ---------------------------------------------------------------------------
extern "C" void kernel_launch(void* const* d_in, const int* in_sizes, int n_in,
                              void* d_out, int out_size) {
    const float* x     = (const float*)d_in[0];
    const void*  ei    = d_in[1];
    const void*  batch = d_in[2];
    const float* W1    = (const float*)d_in[3];
    const float* b1    = (const float*)d_in[4];
    const float* W2    = (const float*)d_in[5];
    const float* b2    = (const float*)d_in[6];
    const float* lw1   = (const float*)d_in[7];
    const float* lb1   = (const float*)d_in[8];
    const float* lw2   = (const float*)d_in[9];
    const float* lb2   = (const float*)d_in[10];
    float* out = (float*)d_out;

    const int T = 256;
    const int gN  = (NN + T - 1) / T;
    const int gE2 = (NE / 2 + T - 1) / T;
    const int gG  = (NN * 4 + T - 1) / T;
    const int gX  = (NN / 4 + T - 1) / T;      // 98

    k_setup<<<gN, T>>>((const int*)ei);
    k_cvt_deg<<<gE2, T>>>(ei);

    // CSR build (+ dinv fused into scan1; scan2+3 merged)
    k_scan1<<<NBLK, 256>>>();
    k_scan23<<<gN, T>>>();

    // placement + xw1 fused (independent work, one launch)
    k_place_xw1<<<G_PLACE + gX, T>>>(x, W1);

    // layer 1 (+ fused relu @ W2)
    k_gather1<<<gG, T>>>(b1, W2);

    // layer 2 (+ fused relu + pool)
    k_gather2<<<gG, T>>>(b2, batch);

    // head
    k_mlp<<<NG, 128>>>(lw1, lb1, lw2, lb2, out);

    (void)in_sizes; (void)n_in; (void)out_size;
}